// round 1
// baseline (speedup 1.0000x reference)
#include <cuda_runtime.h>
#include <math.h>
#include <float.h>

#define NN 256
#define EMAX 8704
#define SLOTS 56

// ---------------- scratch (no allocations allowed) ----------------
__device__ float d_xl0[NN * 128];
__device__ float d_xr0[NN * 128];
__device__ float d_xlM[NN * 128];
__device__ float d_xrM[NN * 128];
__device__ int   d_rowptr[NN + 1];
__device__ int   d_csrc[EMAX];

__device__ __forceinline__ float warp_sum(float v) {
    v += __shfl_xor_sync(0xffffffffu, v, 16);
    v += __shfl_xor_sync(0xffffffffu, v, 8);
    v += __shfl_xor_sync(0xffffffffu, v, 4);
    v += __shfl_xor_sync(0xffffffffu, v, 2);
    v += __shfl_xor_sync(0xffffffffu, v, 1);
    return v;
}

// ---------------- K1: per-row fused precompute ----------------
// Produces xl0/xr0 (baseline GAT1 transforms) and xlM/xrM (masked-row variants).
__global__ void __launch_bounds__(128) k1_precompute(
    const float* __restrict__ x, const float* __restrict__ E_emb,
    const float* __restrict__ node_proj, const float* __restrict__ emb_proj,
    const float* __restrict__ conv_w0, const float* __restrict__ conv_w1,
    const float* __restrict__ conv_b,
    const float* __restrict__ lin2_w, const float* __restrict__ lin2_b,
    const float* __restrict__ masked_proj, const float* __restrict__ normal_proj,
    const float* __restrict__ g1_wl, const float* __restrict__ g1_bl,
    const float* __restrict__ g1_wr, const float* __restrict__ g1_br)
{
    __shared__ float sx[64], sE[64];
    __shared__ float sxp[128], sEp[128];
    __shared__ float sh0[128], shM[128];
    __shared__ float sm0[64], smM[64];
    __shared__ float sp0[64], spM[64];

    int row = blockIdx.x;
    int c = threadIdx.x;

    if (c < 64) sx[c] = x[row * 64 + c];
    else        sE[c - 64] = E_emb[row * 64 + (c - 64)];
    __syncthreads();

    // x_p, E_p : [128]
    {
        float xp = 0.f, Ep = 0.f;
        for (int k = 0; k < 64; k++) {
            xp += sx[k] * node_proj[k * 128 + c];
            Ep += sE[k] * emb_proj[k * 128 + c];
        }
        sxp[c] = xp; sEp[c] = Ep;
    }
    __syncthreads();

    // x_w1 = x_p @ conv_w1 ; bM = E_p @ conv_w0 + conv_b
    {
        float xw1 = 0.f, bM = conv_b[c];
        for (int k = 0; k < 128; k++) {
            xw1 += sxp[k] * conv_w1[k * 128 + c];
            bM  += sEp[k] * conv_w0[k * 128 + c];
        }
        sh0[c] = tanhf(bM + xw1);   // unmasked h
        shM[c] = tanhf(bM);         // masked-row h (row's own x contribution removed)
    }
    __syncthreads();

    // m = h @ lin2_w + lin2_b : [64] for both variants
    if (c < 64) {
        float a = lin2_b[c];
        for (int k = 0; k < 128; k++) a += sh0[k] * lin2_w[k * 64 + c];
        sm0[c] = a;
    } else {
        int cc = c - 64;
        float a = lin2_b[cc];
        for (int k = 0; k < 128; k++) a += shM[k] * lin2_w[k * 64 + cc];
        smM[cc] = a;
    }
    __syncthreads();

    // proj: normal for baseline rows, masked for the substituted row
    if (c < 64) {
        float a = 0.f;
        for (int k = 0; k < 64; k++) a += sm0[k] * normal_proj[k * 64 + c];
        sp0[c] = a;
    } else {
        int cc = c - 64;
        float a = 0.f;
        for (int k = 0; k < 64; k++) a += smM[k] * masked_proj[k * 64 + cc];
        spM[cc] = a;
    }
    __syncthreads();

    // GAT1 source/target transforms for both variants
    {
        float l0 = g1_bl[c], r0 = g1_br[c], lM = g1_bl[c], rM = g1_br[c];
        for (int k = 0; k < 64; k++) {
            float p0 = sp0[k], pM = spM[k];
            float wlv = g1_wl[k * 128 + c], wrv = g1_wr[k * 128 + c];
            l0 += p0 * wlv; r0 += p0 * wrv;
            lM += pM * wlv; rM += pM * wrv;
        }
        d_xl0[row * 128 + c] = l0;
        d_xr0[row * 128 + c] = r0;
        d_xlM[row * 128 + c] = lM;
        d_xrM[row * 128 + c] = rM;
    }
}

// ---------------- K2: CSR by destination ----------------
__global__ void k2_csr(const int* __restrict__ ei, int E)
{
    __shared__ int cnt[NN];
    __shared__ int cur[NN];
    int tid = threadIdx.x;
    cnt[tid] = 0;
    __syncthreads();
    const int* src = ei;
    const int* dst = ei + E;
    for (int e = tid; e < E; e += 256) atomicAdd(&cnt[dst[e]], 1);
    __syncthreads();
    if (tid == 0) {
        int acc = 0;
        for (int n = 0; n < NN; n++) {
            cur[n] = acc;
            d_rowptr[n] = acc;
            acc += cnt[n];
        }
        d_rowptr[NN] = acc;
    }
    __syncthreads();
    for (int e = tid; e < E; e += 256) {
        int pos = atomicAdd(&cur[dst[e]], 1);
        d_csrc[pos] = src[e];
    }
}

// ---------------- K4: per-instance masked-node pipeline ----------------
// blockIdx.x = instance i. Computes g1 at T_i = {i} U in_neighbors(i),
// then GAT2 softmax at target i only, then reconstruction row i.
__global__ void __launch_bounds__(256) k4_main(
    const float* __restrict__ att1, const float* __restrict__ bias1,
    const float* __restrict__ w2l, const float* __restrict__ b2l,
    const float* __restrict__ w2r, const float* __restrict__ b2r,
    const float* __restrict__ att2, const float* __restrict__ bias2,
    const float* __restrict__ recw, const float* __restrict__ recb,
    float* __restrict__ out)
{
    __shared__ float g1buf[SLOTS * 64];
    __shared__ float xl2s[SLOTS * 128];
    __shared__ float headout[512];     // 4 groups x 2 heads x 64
    __shared__ float xr2s[128];
    __shared__ float g2row[64];
    __shared__ int   tgt[SLOTS];
    __shared__ int   slot_of[NN];
    __shared__ int   nslots_sh;

    int i   = blockIdx.x;
    int tid = threadIdx.x;
    int w    = tid >> 5;
    int lane = tid & 31;
    int g = w >> 1;      // target group 0..3
    int h = w & 1;       // head
    int c0 = 2 * lane;

    for (int k = tid; k < NN; k += 256) slot_of[k] = -1;
    __syncthreads();
    if (tid == 0) {
        int ns = 0;
        slot_of[i] = ns; tgt[ns++] = i;   // slot 0 is always node i
        int b = d_rowptr[i], e = d_rowptr[i + 1];
        for (int p = b; p < e; p++) {
            int s = d_csrc[p];
            if (slot_of[s] < 0 && ns < SLOTS) { slot_of[s] = ns; tgt[ns++] = s; }
        }
        nslots_sh = ns;
    }
    __syncthreads();
    int nslots = nslots_sh;

    float a10 = att1[h * 64 + c0];
    float a11 = att1[h * 64 + c0 + 1];

    // ---- Layer 1: GATv2 softmax at each needed target, with row-i substitution ----
    for (int ts = g; ts < nslots; ts += 4) {
        int t = tgt[ts];
        const float* xrrow = (t == i) ? (d_xrM + i * 128) : (d_xr0 + t * 128);
        float xrx = xrrow[h * 64 + c0];
        float xry = xrrow[h * 64 + c0 + 1];

        float m = -3.0e38f, denom = 0.f, accx = 0.f, accy = 0.f;
        int b = d_rowptr[t], e = d_rowptr[t + 1];
        for (int p = b; p < e; p++) {
            int s = d_csrc[p];
            const float* xlrow = (s == i) ? (d_xlM + i * 128) : (d_xl0 + s * 128);
            float xlx = xlrow[h * 64 + c0];
            float xly = xlrow[h * 64 + c0 + 1];
            float t0 = xlx + xrx, t1 = xly + xry;
            t0 = t0 > 0.f ? t0 : 0.2f * t0;
            t1 = t1 > 0.f ? t1 : 0.2f * t1;
            float logit = warp_sum(a10 * t0 + a11 * t1);
            float nm = fmaxf(m, logit);
            float sc = __expf(m - nm);
            float wt = __expf(logit - nm);
            denom = denom * sc + wt;
            accx  = accx  * sc + wt * xlx;
            accy  = accy  * sc + wt * xly;
            m = nm;
        }
        float inv = 1.f / (denom + 1e-16f);
        float* ho = headout + g * 128 + h * 64;
        ho[c0]     = accx * inv;
        ho[c0 + 1] = accy * inv;
        asm volatile("bar.sync %0, 64;" :: "r"(g + 1) : "memory");
        if (h == 0) {
            const float* h0p = headout + g * 128;
            const float* h1p = h0p + 64;
            float v0 = 0.5f * (h0p[c0]     + h1p[c0])     + bias1[c0];
            float v1 = 0.5f * (h0p[c0 + 1] + h1p[c0 + 1]) + bias1[c0 + 1];
            g1buf[ts * 64 + c0]     = v0 > 0.f ? v0 : expm1f(v0);
            g1buf[ts * 64 + c0 + 1] = v1 > 0.f ? v1 : expm1f(v1);
        }
        asm volatile("bar.sync %0, 64;" :: "r"(g + 1) : "memory");
    }
    __syncthreads();

    // ---- Layer 2 source transforms for every slot (srcs of edges into i) ----
    for (int ts = g; ts < nslots; ts += 4) {
        float sxv = b2l[h * 64 + c0];
        float syv = b2l[h * 64 + c0 + 1];
        const float* grow = g1buf + ts * 64;
        for (int k = 0; k < 64; k++) {
            float gk = grow[k];
            sxv += gk * w2l[k * 128 + h * 64 + c0];
            syv += gk * w2l[k * 128 + h * 64 + c0 + 1];
        }
        xl2s[ts * 128 + h * 64 + c0]     = sxv;
        xl2s[ts * 128 + h * 64 + c0 + 1] = syv;
    }
    // target transform for node i (slot 0)
    if (g == 0) {
        float sxv = b2r[h * 64 + c0];
        float syv = b2r[h * 64 + c0 + 1];
        for (int k = 0; k < 64; k++) {
            float gk = g1buf[k];
            sxv += gk * w2r[k * 128 + h * 64 + c0];
            syv += gk * w2r[k * 128 + h * 64 + c0 + 1];
        }
        xr2s[h * 64 + c0]     = sxv;
        xr2s[h * 64 + c0 + 1] = syv;
    }
    __syncthreads();

    // ---- Layer 2 softmax at target i ----
    if (g == 0) {
        float xrx = xr2s[h * 64 + c0];
        float xry = xr2s[h * 64 + c0 + 1];
        float a20 = att2[h * 64 + c0];
        float a21 = att2[h * 64 + c0 + 1];
        float m = -3.0e38f, denom = 0.f, accx = 0.f, accy = 0.f;
        int b = d_rowptr[i], e = d_rowptr[i + 1];
        for (int p = b; p < e; p++) {
            int s  = d_csrc[p];
            int sl = slot_of[s];
            float xlx = xl2s[sl * 128 + h * 64 + c0];
            float xly = xl2s[sl * 128 + h * 64 + c0 + 1];
            float t0 = xlx + xrx, t1 = xly + xry;
            t0 = t0 > 0.f ? t0 : 0.2f * t0;
            t1 = t1 > 0.f ? t1 : 0.2f * t1;
            float logit = warp_sum(a20 * t0 + a21 * t1);
            float nm = fmaxf(m, logit);
            float sc = __expf(m - nm);
            float wt = __expf(logit - nm);
            denom = denom * sc + wt;
            accx  = accx  * sc + wt * xlx;
            accy  = accy  * sc + wt * xly;
            m = nm;
        }
        float inv = 1.f / (denom + 1e-16f);
        float* ho = headout + h * 64;
        ho[c0]     = accx * inv;
        ho[c0 + 1] = accy * inv;
        asm volatile("bar.sync 1, 64;" ::: "memory");
        if (h == 0) {
            float v0 = 0.5f * (headout[c0]     + headout[64 + c0])     + bias2[c0];
            float v1 = 0.5f * (headout[c0 + 1] + headout[64 + c0 + 1]) + bias2[c0 + 1];
            g2row[c0]     = v0 > 0.f ? v0 : expm1f(v0);
            g2row[c0 + 1] = v1 > 0.f ? v1 : expm1f(v1);
        }
    }
    __syncthreads();

    // ---- Reconstruction row i ----
    if (tid < 64) {
        float a = recb[tid];
        for (int cc = 0; cc < 64; cc++) a += g2row[cc] * recw[cc * 64 + tid];
        out[i * 64 + tid] = tanhf(a);
    }
}

// ---------------- launch ----------------
extern "C" void kernel_launch(void* const* d_in, const int* in_sizes, int n_in,
                              void* d_out, int out_size)
{
    const float* x          = (const float*)d_in[0];
    const float* E_emb      = (const float*)d_in[1];
    const int*   edge_index = (const int*)  d_in[2];
    const float* node_proj  = (const float*)d_in[3];
    const float* emb_proj   = (const float*)d_in[4];
    const float* conv_w0    = (const float*)d_in[5];
    const float* conv_w1    = (const float*)d_in[6];
    const float* conv_b     = (const float*)d_in[7];
    const float* lin2_w     = (const float*)d_in[8];
    const float* lin2_b     = (const float*)d_in[9];
    const float* masked_proj= (const float*)d_in[10];
    const float* normal_proj= (const float*)d_in[11];
    const float* g1_wl      = (const float*)d_in[12];
    const float* g1_bl      = (const float*)d_in[13];
    const float* g1_wr      = (const float*)d_in[14];
    const float* g1_br      = (const float*)d_in[15];
    const float* g1_att     = (const float*)d_in[16];
    const float* g1_bias    = (const float*)d_in[17];
    const float* g2_wl      = (const float*)d_in[18];
    const float* g2_bl      = (const float*)d_in[19];
    const float* g2_wr      = (const float*)d_in[20];
    const float* g2_br      = (const float*)d_in[21];
    const float* g2_att     = (const float*)d_in[22];
    const float* g2_bias    = (const float*)d_in[23];
    const float* rec_w      = (const float*)d_in[24];
    const float* rec_b      = (const float*)d_in[25];
    float* out = (float*)d_out;

    int E = in_sizes[2] / 2;

    k1_precompute<<<NN, 128>>>(x, E_emb, node_proj, emb_proj,
                               conv_w0, conv_w1, conv_b,
                               lin2_w, lin2_b, masked_proj, normal_proj,
                               g1_wl, g1_bl, g1_wr, g1_br);
    k2_csr<<<1, 256>>>(edge_index, E);
    k4_main<<<NN, 256>>>(g1_att, g1_bias,
                         g2_wl, g2_bl, g2_wr, g2_br,
                         g2_att, g2_bias, rec_w, rec_b, out);
}

// round 2
// speedup vs baseline: 1.4575x; 1.4575x over previous
#include <cuda_runtime.h>
#include <math.h>
#include <float.h>

#define NN 256
#define EMAX 8704
#define DMAX 40

// ---------------- scratch ----------------
__device__ float d_xl0[NN * 128];
__device__ float d_xr0[NN * 128];
__device__ float d_xlM[NN * 128];
__device__ float d_xrM[NN * 128];
__device__ float d_xl20[NN * 128];
__device__ int   d_rowptr[NN + 1];
__device__ int   d_csrc[EMAX];
__device__ int   d_colptr[NN + 1];
__device__ int   d_cdst[EMAX];

__device__ __forceinline__ float warp_sum(float v) {
    v += __shfl_xor_sync(0xffffffffu, v, 16);
    v += __shfl_xor_sync(0xffffffffu, v, 8);
    v += __shfl_xor_sync(0xffffffffu, v, 4);
    v += __shfl_xor_sync(0xffffffffu, v, 2);
    v += __shfl_xor_sync(0xffffffffu, v, 1);
    return v;
}
__device__ __forceinline__ float warp_max(float v) {
    v = fmaxf(v, __shfl_xor_sync(0xffffffffu, v, 16));
    v = fmaxf(v, __shfl_xor_sync(0xffffffffu, v, 8));
    v = fmaxf(v, __shfl_xor_sync(0xffffffffu, v, 4));
    v = fmaxf(v, __shfl_xor_sync(0xffffffffu, v, 2));
    v = fmaxf(v, __shfl_xor_sync(0xffffffffu, v, 1));
    return v;
}

// Two-pass GATv2 softmax over one target's in-edges for one head.
// xlb: base xl pointer pre-offset by channel (stride 128 per node).
// xls: substituted row (pre-offset) used when source == isub.
__device__ __forceinline__ float2 gat_target(
    const int* __restrict__ csrc, int b, int deg,
    const float* __restrict__ xlb, const float* __restrict__ xls, int isub,
    float xrx, float xry, float a0, float a1, int lane)
{
    float lg0 = -1e30f, lg1 = -1e30f;
    for (int j = 0; j < deg; j++) {
        int s = csrc[b + j];
        const float* row = (s == isub) ? xls : (xlb + s * 128);
        float xlx = row[0], xly = row[1];
        float t0 = xlx + xrx; t0 = t0 > 0.f ? t0 : 0.2f * t0;
        float t1 = xly + xry; t1 = t1 > 0.f ? t1 : 0.2f * t1;
        float l = warp_sum(a0 * t0 + a1 * t1);
        if ((j & 31) == lane) { if (j < 32) lg0 = l; else lg1 = l; }
    }
    float m = warp_max(fmaxf(lg0, lg1));
    float denom = 0.f, ax = 0.f, ay = 0.f;
    for (int j = 0; j < deg; j++) {
        float l = __shfl_sync(0xffffffffu, (j < 32) ? lg0 : lg1, j & 31);
        float w = __expf(l - m);
        int s = csrc[b + j];
        const float* row = (s == isub) ? xls : (xlb + s * 128);
        denom += w;
        ax += w * row[0];
        ay += w * row[1];
    }
    float inv = 1.f / (denom + 1e-16f);
    return make_float2(ax * inv, ay * inv);
}

// ---------------- K1: blocked fused precompute (2 rows / CTA) ----------------
__device__ __forceinline__ void stage(const float* __restrict__ g, float* s, int n, int tid) {
    const float4* g4 = (const float4*)g;
    float4* s4 = (float4*)s;
    #pragma unroll 4
    for (int idx = tid; idx < (n >> 2); idx += 256) s4[idx] = g4[idx];
}

__global__ void __launch_bounds__(256) k1_precompute(
    const float* __restrict__ x, const float* __restrict__ E_emb,
    const float* __restrict__ node_proj, const float* __restrict__ emb_proj,
    const float* __restrict__ conv_w0, const float* __restrict__ conv_w1,
    const float* __restrict__ conv_b,
    const float* __restrict__ lin2_w, const float* __restrict__ lin2_b,
    const float* __restrict__ masked_proj, const float* __restrict__ normal_proj,
    const float* __restrict__ g1_wl, const float* __restrict__ g1_bl,
    const float* __restrict__ g1_wr, const float* __restrict__ g1_br)
{
    extern __shared__ float smem[];
    float* sW  = smem;          // 16384
    float* sx  = sW  + 16384;   // 128
    float* sE  = sx  + 128;     // 128
    float* sxp = sE  + 128;     // 256
    float* sEp = sxp + 256;     // 256
    float* sh0 = sEp + 256;     // 256
    float* shM = sh0 + 256;     // 256
    float* sm0 = shM + 256;     // 128
    float* smM = sm0 + 128;     // 128
    float* sp0 = smM + 128;     // 128
    float* spM = sp0 + 128;     // 128
    float* sTmp= spM + 128;     // 512

    int tid = threadIdx.x;
    int r0 = blockIdx.x * 2;

    // row inputs (2 rows contiguous)
    if (tid < 128) sx[tid] = x[r0 * 64 + tid];
    else           sE[tid - 128] = E_emb[r0 * 64 + (tid - 128)];

    // S1: x_p, E_p
    stage(node_proj, sW, 8192, tid);
    stage(emb_proj,  sW + 8192, 8192, tid);
    __syncthreads();
    if (tid < 128) {
        int c = tid; float a0 = 0.f, a1 = 0.f;
        #pragma unroll
        for (int k = 0; k < 64; k++) {
            float w = sW[k * 128 + c];
            a0 += sx[k] * w; a1 += sx[64 + k] * w;
        }
        sxp[c] = a0; sxp[128 + c] = a1;
    } else {
        int c = tid - 128; float a0 = 0.f, a1 = 0.f;
        #pragma unroll
        for (int k = 0; k < 64; k++) {
            float w = sW[8192 + k * 128 + c];
            a0 += sE[k] * w; a1 += sE[64 + k] * w;
        }
        sEp[c] = a0; sEp[128 + c] = a1;
    }
    __syncthreads();

    // S2a: xw1 = x_p @ conv_w1 (k-split partials)
    stage(conv_w1, sW, 16384, tid);
    __syncthreads();
    {
        int c = tid & 127, half = tid >> 7;
        float p0 = 0.f, p1 = 0.f;
        #pragma unroll
        for (int kk = 0; kk < 64; kk++) {
            int k = half * 64 + kk;
            float w = sW[k * 128 + c];
            p0 += sxp[k] * w; p1 += sxp[128 + k] * w;
        }
        sTmp[tid] = p0; sTmp[256 + tid] = p1;
    }
    __syncthreads();
    float xw10 = 0.f, xw11 = 0.f;
    if (tid < 128) {
        xw10 = sTmp[tid] + sTmp[tid + 128];
        xw11 = sTmp[256 + tid] + sTmp[384 + tid];
    }
    // S2b: bM = E_p @ conv_w0 + conv_b
    stage(conv_w0, sW, 16384, tid);
    __syncthreads();
    {
        int c = tid & 127, half = tid >> 7;
        float p0 = 0.f, p1 = 0.f;
        #pragma unroll
        for (int kk = 0; kk < 64; kk++) {
            int k = half * 64 + kk;
            float w = sW[k * 128 + c];
            p0 += sEp[k] * w; p1 += sEp[128 + k] * w;
        }
        sTmp[tid] = p0; sTmp[256 + tid] = p1;
    }
    __syncthreads();
    if (tid < 128) {
        float cb = conv_b[tid];
        float bM0 = sTmp[tid] + sTmp[tid + 128] + cb;
        float bM1 = sTmp[256 + tid] + sTmp[384 + tid] + cb;
        sh0[tid] = tanhf(bM0 + xw10);  shM[tid] = tanhf(bM0);
        sh0[128 + tid] = tanhf(bM1 + xw11); shM[128 + tid] = tanhf(bM1);
    }
    __syncthreads();

    // S3: m = h @ lin2_w + lin2_b (both variants, k-split)
    stage(lin2_w, sW, 8192, tid);
    __syncthreads();
    {
        int v = tid >> 7, kh = (tid >> 6) & 1, c = tid & 63;
        const float* hs = v ? shM : sh0;
        float p0 = 0.f, p1 = 0.f;
        #pragma unroll
        for (int kk = 0; kk < 64; kk++) {
            int k = kh * 64 + kk;
            float w = sW[k * 64 + c];
            p0 += hs[k] * w; p1 += hs[128 + k] * w;
        }
        sTmp[tid] = p0; sTmp[256 + tid] = p1;
    }
    __syncthreads();
    if (tid < 128) {
        int v = tid >> 6, c = tid & 63;
        int base = v * 128 + c;
        float lb = lin2_b[c];
        float q0 = sTmp[base] + sTmp[base + 64] + lb;
        float q1 = sTmp[256 + base] + sTmp[256 + base + 64] + lb;
        float* d = v ? smM : sm0;
        d[c] = q0; d[64 + c] = q1;
    }
    __syncthreads();

    // S4: proj (normal for baseline, masked for variant)
    stage(normal_proj, sW, 4096, tid);
    stage(masked_proj, sW + 4096, 4096, tid);
    __syncthreads();
    if (tid < 128) {
        int v = tid >> 6, c = tid & 63;
        const float* s = v ? smM : sm0;
        const float* W = sW + v * 4096;
        float a0 = 0.f, a1 = 0.f;
        #pragma unroll
        for (int k = 0; k < 64; k++) {
            float w = W[k * 64 + c];
            a0 += s[k] * w; a1 += s[64 + k] * w;
        }
        float* d = v ? spM : sp0;
        d[c] = a0; d[64 + c] = a1;
    }
    __syncthreads();

    // S5: GAT1 transforms
    stage(g1_wl, sW, 8192, tid);
    stage(g1_wr, sW + 8192, 8192, tid);
    __syncthreads();
    {
        int half = tid >> 7, c = tid & 127;
        const float* W = sW + half * 8192;
        float a00 = 0.f, a01 = 0.f, aM0 = 0.f, aM1 = 0.f;
        #pragma unroll
        for (int k = 0; k < 64; k++) {
            float w = W[k * 128 + c];
            a00 += sp0[k] * w; a01 += sp0[64 + k] * w;
            aM0 += spM[k] * w; aM1 += spM[64 + k] * w;
        }
        float bb = half ? g1_br[c] : g1_bl[c];
        float* o0 = half ? d_xr0 : d_xl0;
        float* oM = half ? d_xrM : d_xlM;
        o0[r0 * 128 + c] = a00 + bb; o0[(r0 + 1) * 128 + c] = a01 + bb;
        oM[r0 * 128 + c] = aM0 + bb; oM[(r0 + 1) * 128 + c] = aM1 + bb;
    }
}

// ---------------- K2: CSR (by dst) + CSC (by src), parallel scan ----------------
__global__ void __launch_bounds__(256) k2_csr(const int* __restrict__ ei, int E)
{
    __shared__ int c1[NN], c2[NN], cur1[NN], cur2[NN];
    __shared__ int ws[16];
    int tid = threadIdx.x, lane = tid & 31, wid = tid >> 5;
    c1[tid] = 0; c2[tid] = 0;
    __syncthreads();
    const int* src = ei;
    const int* dst = ei + E;
    for (int e = tid; e < E; e += NN) {
        atomicAdd(&c1[dst[e]], 1);
        atomicAdd(&c2[src[e]], 1);
    }
    __syncthreads();
    int v1 = c1[tid], v2 = c2[tid];
    int x1 = v1, x2 = v2;
    #pragma unroll
    for (int d = 1; d < 32; d <<= 1) {
        int y1 = __shfl_up_sync(0xffffffffu, x1, d);
        int y2 = __shfl_up_sync(0xffffffffu, x2, d);
        if (lane >= d) { x1 += y1; x2 += y2; }
    }
    if (lane == 31) { ws[wid] = x1; ws[8 + wid] = x2; }
    __syncthreads();
    if (tid == 0) {
        int a = 0, b = 0;
        for (int w = 0; w < 8; w++) {
            int t1 = ws[w], t2 = ws[8 + w];
            ws[w] = a; ws[8 + w] = b;
            a += t1; b += t2;
        }
    }
    __syncthreads();
    int ex1 = ws[wid] + x1 - v1;
    int ex2 = ws[8 + wid] + x2 - v2;
    d_rowptr[tid] = ex1; d_colptr[tid] = ex2;
    cur1[tid] = ex1; cur2[tid] = ex2;
    if (tid == NN - 1) { d_rowptr[NN] = ex1 + v1; d_colptr[NN] = ex2 + v2; }
    __syncthreads();
    for (int e = tid; e < E; e += NN) {
        int p1 = atomicAdd(&cur1[dst[e]], 1); d_csrc[p1] = src[e];
        int p2 = atomicAdd(&cur2[src[e]], 1); d_cdst[p2] = dst[e];
    }
}

// ---------------- K3: baseline g1_0 + xl2_0 for all nodes ----------------
__global__ void __launch_bounds__(256) k3_baseline(
    const float* __restrict__ att1, const float* __restrict__ bias1,
    const float* __restrict__ w2l, const float* __restrict__ b2l)
{
    __shared__ float hb[4 * 128];
    __shared__ float sg1[4 * 64];
    int tid = threadIdx.x, lane = tid & 31, wid = tid >> 5;
    int pair = wid >> 1, h = wid & 1;
    int t = blockIdx.x * 4 + pair;
    int c0 = 2 * lane;
    int choff = h * 64 + c0;

    int b = d_rowptr[t], deg = d_rowptr[t + 1] - b;
    float2 xr = *(const float2*)(d_xr0 + t * 128 + choff);
    float a0 = att1[choff], a1 = att1[choff + 1];
    float2 o = gat_target(d_csrc, b, deg, d_xl0 + choff, d_xl0 + choff, -1,
                          xr.x, xr.y, a0, a1, lane);
    hb[pair * 128 + choff] = o.x; hb[pair * 128 + choff + 1] = o.y;
    asm volatile("bar.sync %0, 64;" :: "r"(pair + 1) : "memory");
    if (h == 0) {
        float v0 = 0.5f * (hb[pair * 128 + c0] + hb[pair * 128 + 64 + c0]) + bias1[c0];
        float v1 = 0.5f * (hb[pair * 128 + c0 + 1] + hb[pair * 128 + 64 + c0 + 1]) + bias1[c0 + 1];
        sg1[pair * 64 + c0]     = v0 > 0.f ? v0 : expm1f(v0);
        sg1[pair * 64 + c0 + 1] = v1 > 0.f ? v1 : expm1f(v1);
    }
    asm volatile("bar.sync %0, 64;" :: "r"(pair + 1) : "memory");
    // xl2_0 = g1_0 @ w2l + b2l
    {
        float sxv = b2l[choff], syv = b2l[choff + 1];
        const float* g = sg1 + pair * 64;
        #pragma unroll 8
        for (int k = 0; k < 64; k++) {
            float gv = g[k];
            sxv += gv * w2l[k * 128 + choff];
            syv += gv * w2l[k * 128 + choff + 1];
        }
        d_xl20[t * 128 + choff] = sxv;
        d_xl20[t * 128 + choff + 1] = syv;
    }
}

// ---------------- K4: per-instance delta pipeline ----------------
__global__ void __launch_bounds__(256) k4_main(
    const float* __restrict__ att1, const float* __restrict__ bias1,
    const float* __restrict__ w2l, const float* __restrict__ b2l,
    const float* __restrict__ w2r, const float* __restrict__ b2r,
    const float* __restrict__ att2, const float* __restrict__ bias2,
    const float* __restrict__ recw, const float* __restrict__ recb,
    float* __restrict__ out)
{
    __shared__ int   innb[NN];
    __shared__ int   didx[NN];
    __shared__ int   dlist[DMAX];
    __shared__ int   nd_sh;
    __shared__ float g1d[DMAX * 64];
    __shared__ float xl2d[DMAX * 128];
    __shared__ float xr2s[128];
    __shared__ float hb[4 * 128];
    __shared__ float g2[64];

    int i = blockIdx.x;
    int tid = threadIdx.x, lane = tid & 31, wid = tid >> 5;
    int pair = wid >> 1, h = wid & 1;
    int c0 = 2 * lane;
    int choff = h * 64 + c0;

    for (int k = tid; k < NN; k += 256) { innb[k] = 0; didx[k] = -1; }
    __syncthreads();
    int b_i = d_rowptr[i], e_i = d_rowptr[i + 1], deg_i = e_i - b_i;
    for (int p = b_i + tid; p < e_i; p += 256) innb[d_csrc[p]] = 1;
    __syncthreads();
    if (tid == 0) {
        int nd = 0;
        dlist[0] = i; didx[i] = 0; nd = 1;
        int cb = d_colptr[i], ce = d_colptr[i + 1];
        for (int p = cb; p < ce; p++) {
            int t = d_cdst[p];
            if ((t == i || innb[t]) && didx[t] < 0 && nd < DMAX) {
                didx[t] = nd; dlist[nd++] = t;
            }
        }
        nd_sh = nd;
    }
    __syncthreads();
    int nd = nd_sh;

    // Phase A: recompute g1 for delta targets (warp-pair per target, per head)
    float a10 = att1[choff], a11 = att1[choff + 1];
    for (int d = pair; d < nd; d += 4) {
        int t = dlist[d];
        float2 xr = (t == i) ? *(const float2*)(d_xrM + i * 128 + choff)
                             : *(const float2*)(d_xr0 + t * 128 + choff);
        int b = d_rowptr[t], deg = d_rowptr[t + 1] - b;
        float2 o = gat_target(d_csrc, b, deg, d_xl0 + choff,
                              d_xlM + i * 128 + choff, i,
                              xr.x, xr.y, a10, a11, lane);
        hb[pair * 128 + choff] = o.x; hb[pair * 128 + choff + 1] = o.y;
        asm volatile("bar.sync %0, 64;" :: "r"(pair + 1) : "memory");
        if (h == 0) {
            float v0 = 0.5f * (hb[pair * 128 + c0] + hb[pair * 128 + 64 + c0]) + bias1[c0];
            float v1 = 0.5f * (hb[pair * 128 + c0 + 1] + hb[pair * 128 + 64 + c0 + 1]) + bias1[c0 + 1];
            g1d[d * 64 + c0]     = v0 > 0.f ? v0 : expm1f(v0);
            g1d[d * 64 + c0 + 1] = v1 > 0.f ? v1 : expm1f(v1);
        }
        asm volatile("bar.sync %0, 64;" :: "r"(pair + 1) : "memory");
    }
    __syncthreads();

    // Phase B: xl2 deltas + xr2 (warp tasks)
    int ntask = nd * 2 + 2;
    for (int task = wid; task < ntask; task += 8) {
        int isxr = (task >= nd * 2);
        int d  = isxr ? 0 : (task >> 1);
        int hh = isxr ? (task - nd * 2) : (task & 1);
        int co = hh * 64 + c0;
        const float* W = isxr ? w2r : w2l;
        const float* bb = isxr ? b2r : b2l;
        float sxv = bb[co], syv = bb[co + 1];
        const float* g = g1d + d * 64;
        #pragma unroll 8
        for (int k = 0; k < 64; k++) {
            float gv = g[k];
            sxv += gv * W[k * 128 + co];
            syv += gv * W[k * 128 + co + 1];
        }
        if (isxr) { xr2s[co] = sxv; xr2s[co + 1] = syv; }
        else      { xl2d[d * 128 + co] = sxv; xl2d[d * 128 + co + 1] = syv; }
    }
    __syncthreads();

    // Phase C: layer-2 softmax at target i (warps 0,1 = heads)
    if (wid < 2) {
        int h2 = wid;
        int co = h2 * 64 + c0;
        float a0 = att2[co], a1 = att2[co + 1];
        float xrx = xr2s[co], xry = xr2s[co + 1];
        float lg0 = -1e30f, lg1 = -1e30f;
        for (int j = 0; j < deg_i; j++) {
            int s = d_csrc[b_i + j];
            int dd = didx[s];
            float xlx, xly;
            if (dd >= 0) { xlx = xl2d[dd * 128 + co]; xly = xl2d[dd * 128 + co + 1]; }
            else { float2 v = *(const float2*)(d_xl20 + s * 128 + co); xlx = v.x; xly = v.y; }
            float t0 = xlx + xrx; t0 = t0 > 0.f ? t0 : 0.2f * t0;
            float t1 = xly + xry; t1 = t1 > 0.f ? t1 : 0.2f * t1;
            float l = warp_sum(a0 * t0 + a1 * t1);
            if ((j & 31) == lane) { if (j < 32) lg0 = l; else lg1 = l; }
        }
        float m = warp_max(fmaxf(lg0, lg1));
        float denom = 0.f, ax = 0.f, ay = 0.f;
        for (int j = 0; j < deg_i; j++) {
            float l = __shfl_sync(0xffffffffu, (j < 32) ? lg0 : lg1, j & 31);
            float w = __expf(l - m);
            int s = d_csrc[b_i + j];
            int dd = didx[s];
            float xlx, xly;
            if (dd >= 0) { xlx = xl2d[dd * 128 + co]; xly = xl2d[dd * 128 + co + 1]; }
            else { float2 v = *(const float2*)(d_xl20 + s * 128 + co); xlx = v.x; xly = v.y; }
            denom += w; ax += w * xlx; ay += w * xly;
        }
        float inv = 1.f / (denom + 1e-16f);
        hb[co] = ax * inv; hb[co + 1] = ay * inv;
        asm volatile("bar.sync 5, 64;" ::: "memory");
        if (h2 == 0) {
            float v0 = 0.5f * (hb[c0] + hb[64 + c0]) + bias2[c0];
            float v1 = 0.5f * (hb[c0 + 1] + hb[64 + c0 + 1]) + bias2[c0 + 1];
            g2[c0]     = v0 > 0.f ? v0 : expm1f(v0);
            g2[c0 + 1] = v1 > 0.f ? v1 : expm1f(v1);
        }
    }
    __syncthreads();

    // reconstruction row i
    if (tid < 64) {
        float a = recb[tid];
        #pragma unroll 8
        for (int c = 0; c < 64; c++) a += g2[c] * recw[c * 64 + tid];
        out[i * 64 + tid] = tanhf(a);
    }
}

// ---------------- launch ----------------
extern "C" void kernel_launch(void* const* d_in, const int* in_sizes, int n_in,
                              void* d_out, int out_size)
{
    const float* x          = (const float*)d_in[0];
    const float* E_emb      = (const float*)d_in[1];
    const int*   edge_index = (const int*)  d_in[2];
    const float* node_proj  = (const float*)d_in[3];
    const float* emb_proj   = (const float*)d_in[4];
    const float* conv_w0    = (const float*)d_in[5];
    const float* conv_w1    = (const float*)d_in[6];
    const float* conv_b     = (const float*)d_in[7];
    const float* lin2_w     = (const float*)d_in[8];
    const float* lin2_b     = (const float*)d_in[9];
    const float* masked_proj= (const float*)d_in[10];
    const float* normal_proj= (const float*)d_in[11];
    const float* g1_wl      = (const float*)d_in[12];
    const float* g1_bl      = (const float*)d_in[13];
    const float* g1_wr      = (const float*)d_in[14];
    const float* g1_br      = (const float*)d_in[15];
    const float* g1_att     = (const float*)d_in[16];
    const float* g1_bias    = (const float*)d_in[17];
    const float* g2_wl      = (const float*)d_in[18];
    const float* g2_bl      = (const float*)d_in[19];
    const float* g2_wr      = (const float*)d_in[20];
    const float* g2_br      = (const float*)d_in[21];
    const float* g2_att     = (const float*)d_in[22];
    const float* g2_bias    = (const float*)d_in[23];
    const float* rec_w      = (const float*)d_in[24];
    const float* rec_b      = (const float*)d_in[25];
    float* out = (float*)d_out;

    int E = in_sizes[2] / 2;

    cudaFuncSetAttribute(k1_precompute, cudaFuncAttributeMaxDynamicSharedMemorySize, 74752);

    k1_precompute<<<NN / 2, 256, 74752>>>(x, E_emb, node_proj, emb_proj,
                                          conv_w0, conv_w1, conv_b,
                                          lin2_w, lin2_b, masked_proj, normal_proj,
                                          g1_wl, g1_bl, g1_wr, g1_br);
    k2_csr<<<1, 256>>>(edge_index, E);
    k3_baseline<<<NN / 4, 256>>>(g1_att, g1_bias, g2_wl, g2_bl);
    k4_main<<<NN, 256>>>(g1_att, g1_bias,
                         g2_wl, g2_bl, g2_wr, g2_br,
                         g2_att, g2_bias, rec_w, rec_b, out);
}

// round 4
// speedup vs baseline: 1.5664x; 1.0747x over previous
#include <cuda_runtime.h>
#include <math.h>
#include <float.h>

#define NN 256
#define EMAX 8704
#define DMAX 16

// ---------------- scratch ----------------
__device__ __align__(16) float d_xl0[NN * 128];
__device__ __align__(16) float d_xr0[NN * 128];
__device__ __align__(16) float d_xlM[NN * 128];
__device__ __align__(16) float d_xrM[NN * 128];
__device__ __align__(16) float d_xl20[NN * 128];
__device__ int   d_rowptr[NN + 1];
__device__ int   d_csrc[EMAX];
__device__ int   d_colptr[NN + 1];
__device__ int   d_cdst[EMAX];

__device__ __forceinline__ float warp_sum(float v) {
    v += __shfl_xor_sync(0xffffffffu, v, 16);
    v += __shfl_xor_sync(0xffffffffu, v, 8);
    v += __shfl_xor_sync(0xffffffffu, v, 4);
    v += __shfl_xor_sync(0xffffffffu, v, 2);
    v += __shfl_xor_sync(0xffffffffu, v, 1);
    return v;
}
__device__ __forceinline__ float warp_max(float v) {
    v = fmaxf(v, __shfl_xor_sync(0xffffffffu, v, 16));
    v = fmaxf(v, __shfl_xor_sync(0xffffffffu, v, 8));
    v = fmaxf(v, __shfl_xor_sync(0xffffffffu, v, 4));
    v = fmaxf(v, __shfl_xor_sync(0xffffffffu, v, 2));
    v = fmaxf(v, __shfl_xor_sync(0xffffffffu, v, 1));
    return v;
}

// GATv2 softmax for one (target, head). Pass 1: lane = edge (each lane does its
// own 64-ch dot, fully parallel, no shuffles). Pass 2: lane = channel-pair.
// rowfn(s) returns the 64-ch head slice of source s's xl row (8B-aligned).
template <typename RowFn>
__device__ __forceinline__ float2 gat_head(
    const int* __restrict__ csrc, int b, int deg,
    RowFn rowfn, const float* __restrict__ xr, const float* __restrict__ att,
    int lane)
{
    int c0 = 2 * lane;
    float lg1 = -1e30f, lg2 = -1e30f;
    if (lane < deg) {
        const float* r = rowfn(csrc[b + lane]);
        float acc = 0.f;
        #pragma unroll
        for (int c = 0; c < 64; c += 2) {
            float2 v = *(const float2*)(r + c);
            float t0 = v.x + xr[c];     t0 = t0 > 0.f ? t0 : 0.2f * t0;
            float t1 = v.y + xr[c + 1]; t1 = t1 > 0.f ? t1 : 0.2f * t1;
            acc += att[c] * t0 + att[c + 1] * t1;
        }
        lg1 = acc;
    }
    if (32 + lane < deg) {
        const float* r = rowfn(csrc[b + 32 + lane]);
        float acc = 0.f;
        #pragma unroll
        for (int c = 0; c < 64; c += 2) {
            float2 v = *(const float2*)(r + c);
            float t0 = v.x + xr[c];     t0 = t0 > 0.f ? t0 : 0.2f * t0;
            float t1 = v.y + xr[c + 1]; t1 = t1 > 0.f ? t1 : 0.2f * t1;
            acc += att[c] * t0 + att[c + 1] * t1;
        }
        lg2 = acc;
    }
    float m = warp_max(fmaxf(lg1, lg2));
    float w1 = (lane < deg)      ? __expf(lg1 - m) : 0.f;
    float w2 = (32 + lane < deg) ? __expf(lg2 - m) : 0.f;
    float denom = warp_sum(w1 + w2);

    float ax = 0.f, ay = 0.f;
    for (int j = 0; j < deg; j++) {
        float wj = __shfl_sync(0xffffffffu, (j < 32) ? w1 : w2, j & 31);
        const float* r = rowfn(csrc[b + j]);
        float2 v = *(const float2*)(r + c0);
        ax += wj * v.x; ay += wj * v.y;
    }
    float inv = 1.f / (denom + 1e-16f);
    return make_float2(ax * inv, ay * inv);
}

// ---------------- K1: fused precompute, 4 rows/CTA, 3 staging phases ----------
__device__ __forceinline__ void stage(const float* __restrict__ g, float* s, int n, int tid) {
    const float4* g4 = (const float4*)g;
    float4* s4 = (float4*)s;
    #pragma unroll 4
    for (int idx = tid; idx < (n >> 2); idx += 256) s4[idx] = g4[idx];
}

__global__ void __launch_bounds__(256) k1_precompute(
    const float* __restrict__ x, const float* __restrict__ E_emb,
    const float* __restrict__ node_proj, const float* __restrict__ emb_proj,
    const float* __restrict__ conv_w0, const float* __restrict__ conv_w1,
    const float* __restrict__ conv_b,
    const float* __restrict__ lin2_w, const float* __restrict__ lin2_b,
    const float* __restrict__ masked_proj, const float* __restrict__ normal_proj,
    const float* __restrict__ g1_wl, const float* __restrict__ g1_bl,
    const float* __restrict__ g1_wr, const float* __restrict__ g1_br)
{
    extern __shared__ __align__(16) float smem[];
    float* sW   = smem;           // 32768
    float* sx   = sW + 32768;     // 256
    float* sE   = sx + 256;       // 256
    float* sxp  = sE + 256;       // 512
    float* sEp  = sxp + 512;      // 512
    float* sh0  = sEp + 512;      // 512
    float* shM  = sh0 + 512;      // 512
    float* sm0  = shM + 512;      // 256
    float* smM  = sm0 + 256;      // 256
    float* sp0  = smM + 256;      // 256
    float* spM  = sp0 + 256;      // 256
    float* sTmp = spM + 256;      // 1024

    int tid = threadIdx.x;
    int r0 = blockIdx.x * 4;

    sx[tid] = x[r0 * 64 + tid];
    sE[tid] = E_emb[r0 * 64 + tid];

    // --- phase 1 staging: node_proj + emb_proj ---
    stage(node_proj, sW, 8192, tid);
    stage(emb_proj,  sW + 8192, 8192, tid);
    __syncthreads();
    {
        int half = tid >> 7, c = tid & 127;
        const float* W = sW + half * 8192;
        const float* in = half ? sE : sx;
        float a0 = 0.f, a1 = 0.f, a2 = 0.f, a3 = 0.f;
        #pragma unroll 8
        for (int k = 0; k < 64; k++) {
            float w = W[k * 128 + c];
            a0 += in[k] * w; a1 += in[64 + k] * w;
            a2 += in[128 + k] * w; a3 += in[192 + k] * w;
        }
        float* o = half ? sEp : sxp;
        o[c] = a0; o[128 + c] = a1; o[256 + c] = a2; o[384 + c] = a3;
    }
    __syncthreads();

    // --- phase 2 staging: conv_w1 + conv_w0 ---
    stage(conv_w1, sW, 16384, tid);
    stage(conv_w0, sW + 16384, 16384, tid);
    __syncthreads();
    {
        int half = tid >> 7, c = tid & 127;
        const float* W = sW + half * 16384;
        const float* in = half ? sEp : sxp;
        float a0 = 0.f, a1 = 0.f, a2 = 0.f, a3 = 0.f;
        #pragma unroll 8
        for (int k = 0; k < 128; k++) {
            float w = W[k * 128 + c];
            a0 += in[k] * w; a1 += in[128 + k] * w;
            a2 += in[256 + k] * w; a3 += in[384 + k] * w;
        }
        float* o = sTmp + half * 512;
        o[c] = a0; o[128 + c] = a1; o[256 + c] = a2; o[384 + c] = a3;
    }
    __syncthreads();
    if (tid < 128) {
        float cb = conv_b[tid];
        #pragma unroll
        for (int r = 0; r < 4; r++) {
            float xw1 = sTmp[r * 128 + tid];
            float bM  = sTmp[512 + r * 128 + tid] + cb;
            sh0[r * 128 + tid] = tanhf(bM + xw1);
            shM[r * 128 + tid] = tanhf(bM);
        }
    }
    __syncthreads();

    // --- phase 3 staging: lin2 / normal / masked / g1wl / g1wr ---
    stage(lin2_w,      sW, 8192, tid);
    stage(normal_proj, sW + 8192, 4096, tid);
    stage(masked_proj, sW + 12288, 4096, tid);
    stage(g1_wl,       sW + 16384, 8192, tid);
    stage(g1_wr,       sW + 24576, 8192, tid);
    __syncthreads();

    // S3: m = h @ lin2 + b (k-split by 2, 2 variants, 4 rows)
    {
        int v = tid >> 7, kh = (tid >> 6) & 1, c = tid & 63;
        const float* hs = v ? shM : sh0;
        float a0 = 0.f, a1 = 0.f, a2 = 0.f, a3 = 0.f;
        #pragma unroll 8
        for (int kk = 0; kk < 64; kk++) {
            int k = kh * 64 + kk;
            float w = sW[k * 64 + c];
            a0 += hs[k] * w; a1 += hs[128 + k] * w;
            a2 += hs[256 + k] * w; a3 += hs[384 + k] * w;
        }
        float* o = sTmp + v * 512 + kh * 64;
        o[c] = a0; o[128 + c] = a1; o[256 + c] = a2; o[384 + c] = a3;
    }
    __syncthreads();
    {
        int v = tid >> 7, rp = (tid >> 6) & 1, c = tid & 63;
        float lb = lin2_b[c];
        float* d = v ? smM : sm0;
        #pragma unroll
        for (int rr = 0; rr < 2; rr++) {
            int r = rp * 2 + rr;
            d[r * 64 + c] = sTmp[v * 512 + r * 128 + c] + sTmp[v * 512 + r * 128 + 64 + c] + lb;
        }
    }
    __syncthreads();

    // S4: proj (normal for baseline, masked for variant)
    {
        int v = tid >> 7, rp = (tid >> 6) & 1, c = tid & 63;
        const float* s = v ? smM : sm0;
        const float* W = sW + 8192 + v * 4096;
        float* d = v ? spM : sp0;
        float a0 = 0.f, a1 = 0.f;
        int r = rp * 2;
        #pragma unroll 8
        for (int k = 0; k < 64; k++) {
            float w = W[k * 64 + c];
            a0 += s[r * 64 + k] * w; a1 += s[(r + 1) * 64 + k] * w;
        }
        d[r * 64 + c] = a0; d[(r + 1) * 64 + c] = a1;
    }
    __syncthreads();

    // S5: GAT1 transforms (wl/wr, base/masked, 4 rows)
    {
        int half = tid >> 7, c = tid & 127;
        const float* W = sW + 16384 + half * 8192;
        float b0[4] = {0.f, 0.f, 0.f, 0.f};
        float bm[4] = {0.f, 0.f, 0.f, 0.f};
        #pragma unroll 8
        for (int k = 0; k < 64; k++) {
            float w = W[k * 128 + c];
            #pragma unroll
            for (int r = 0; r < 4; r++) {
                b0[r] += sp0[r * 64 + k] * w;
                bm[r] += spM[r * 64 + k] * w;
            }
        }
        float bb = half ? g1_br[c] : g1_bl[c];
        float* o0 = half ? d_xr0 : d_xl0;
        float* oM = half ? d_xrM : d_xlM;
        #pragma unroll
        for (int r = 0; r < 4; r++) {
            o0[(r0 + r) * 128 + c] = b0[r] + bb;
            oM[(r0 + r) * 128 + c] = bm[r] + bb;
        }
    }
}

// ---------------- K2: CSR (by dst) + CSC (by src) ----------------
__global__ void __launch_bounds__(1024) k2_csr(const int* __restrict__ ei, int E)
{
    __shared__ int c1[NN], c2[NN], cur1[NN], cur2[NN];
    __shared__ int ws[16];
    int tid = threadIdx.x;
    if (tid < NN) { c1[tid] = 0; c2[tid] = 0; }
    __syncthreads();
    const int* src = ei;
    const int* dst = ei + E;
    for (int e = tid; e < E; e += 1024) {
        atomicAdd(&c1[dst[e]], 1);
        atomicAdd(&c2[src[e]], 1);
    }
    __syncthreads();
    if (tid < NN) {
        int lane = tid & 31, wid = tid >> 5;
        int v1 = c1[tid], v2 = c2[tid];
        int x1 = v1, x2 = v2;
        #pragma unroll
        for (int d = 1; d < 32; d <<= 1) {
            int y1 = __shfl_up_sync(0xffffffffu, x1, d);
            int y2 = __shfl_up_sync(0xffffffffu, x2, d);
            if (lane >= d) { x1 += y1; x2 += y2; }
        }
        if (lane == 31) { ws[wid] = x1; ws[8 + wid] = x2; }
    }
    __syncthreads();
    if (tid == 0) {
        int a = 0, b = 0;
        for (int w = 0; w < 8; w++) {
            int t1 = ws[w], t2 = ws[8 + w];
            ws[w] = a; ws[8 + w] = b;
            a += t1; b += t2;
        }
    }
    __syncthreads();
    if (tid < NN) {
        int lane = tid & 31, wid = tid >> 5;
        int v1 = c1[tid], v2 = c2[tid];
        int x1 = v1, x2 = v2;
        #pragma unroll
        for (int d = 1; d < 32; d <<= 1) {
            int y1 = __shfl_up_sync(0xffffffffu, x1, d);
            int y2 = __shfl_up_sync(0xffffffffu, x2, d);
            if (lane >= d) { x1 += y1; x2 += y2; }
        }
        int ex1 = ws[wid] + x1 - v1;
        int ex2 = ws[8 + wid] + x2 - v2;
        d_rowptr[tid] = ex1; d_colptr[tid] = ex2;
        cur1[tid] = ex1; cur2[tid] = ex2;
        if (tid == NN - 1) { d_rowptr[NN] = ex1 + v1; d_colptr[NN] = ex2 + v2; }
    }
    __syncthreads();
    for (int e = tid; e < E; e += 1024) {
        int p1 = atomicAdd(&cur1[dst[e]], 1); d_csrc[p1] = src[e];
        int p2 = atomicAdd(&cur2[src[e]], 1); d_cdst[p2] = dst[e];
    }
}

// ---------------- K3: baseline g1_0 + xl2_0 (4 targets/CTA) ----------------
__global__ void __launch_bounds__(256) k3_baseline(
    const float* __restrict__ att1, const float* __restrict__ bias1,
    const float* __restrict__ w2l, const float* __restrict__ b2l)
{
    __shared__ __align__(16) float hA[4 * 128];
    __shared__ __align__(16) float sg1[4 * 64];
    int tid = threadIdx.x, lane = tid & 31, wid = tid >> 5;
    int pair = wid >> 1, h = wid & 1;
    int t = blockIdx.x * 4 + pair;
    int hoff = h * 64;
    int c0 = 2 * lane;

    {
        int b = d_rowptr[t], deg = d_rowptr[t + 1] - b;
        auto rowfn = [&](int s) { return d_xl0 + s * 128 + hoff; };
        float2 o = gat_head(d_csrc, b, deg, rowfn,
                            d_xr0 + t * 128 + hoff, att1 + hoff, lane);
        hA[pair * 128 + hoff + c0] = o.x;
        hA[pair * 128 + hoff + c0 + 1] = o.y;
    }
    __syncthreads();
    {
        int p = tid >> 6, c = tid & 63;
        float v = 0.5f * (hA[p * 128 + c] + hA[p * 128 + 64 + c]) + bias1[c];
        sg1[p * 64 + c] = v > 0.f ? v : expm1f(v);
    }
    __syncthreads();
    {
        float sxv = b2l[hoff + c0], syv = b2l[hoff + c0 + 1];
        const float* g = sg1 + pair * 64;
        #pragma unroll 8
        for (int k = 0; k < 64; k++) {
            float gv = g[k];
            sxv += gv * w2l[k * 128 + hoff + c0];
            syv += gv * w2l[k * 128 + hoff + c0 + 1];
        }
        d_xl20[t * 128 + hoff + c0] = sxv;
        d_xl20[t * 128 + hoff + c0 + 1] = syv;
    }
}

// ---------------- K4: per-instance delta pipeline ----------------
__global__ void __launch_bounds__(256) k4_main(
    const float* __restrict__ att1, const float* __restrict__ bias1,
    const float* __restrict__ w2l, const float* __restrict__ b2l,
    const float* __restrict__ w2r, const float* __restrict__ b2r,
    const float* __restrict__ att2, const float* __restrict__ bias2,
    const float* __restrict__ recw, const float* __restrict__ recb,
    float* __restrict__ out)
{
    __shared__ int   innb[NN];
    __shared__ int   didx[NN];
    __shared__ int   dlist[DMAX];
    __shared__ int   cdsts[64];
    __shared__ int   nd_sh;
    __shared__ __align__(16) float hA[DMAX * 128];
    __shared__ __align__(16) float g1d[DMAX * 64];
    __shared__ __align__(16) float xl2d[DMAX * 128];
    __shared__ __align__(16) float xr2s[128];
    __shared__ __align__(16) float hC[128];
    __shared__ __align__(16) float g2[64];

    int i = blockIdx.x;
    int tid = threadIdx.x, lane = tid & 31, wid = tid >> 5;
    int c0 = 2 * lane;

    for (int k = tid; k < NN; k += 256) { innb[k] = 0; didx[k] = -1; }
    __syncthreads();
    int b_i = d_rowptr[i], e_i = d_rowptr[i + 1], deg_i = e_i - b_i;
    for (int p = b_i + tid; p < e_i; p += 256) innb[d_csrc[p]] = 1;
    int cb = d_colptr[i], ce = d_colptr[i + 1];
    int odeg = min(ce - cb, 64);
    for (int p = tid; p < odeg; p += 256) cdsts[p] = d_cdst[cb + p];
    __syncthreads();
    if (tid == 0) {
        int nd = 1;
        dlist[0] = i; didx[i] = 0;
        for (int p = 0; p < odeg; p++) {
            int t = cdsts[p];
            if ((t == i || innb[t]) && didx[t] < 0 && nd < DMAX) {
                didx[t] = nd; dlist[nd++] = t;
            }
        }
        nd_sh = nd;
    }
    __syncthreads();
    int nd = nd_sh;

    // Phase A: layer-1 GAT at delta targets, warp = (target, head)
    for (int task = wid; task < nd * 2; task += 8) {
        int d = task >> 1, h = task & 1;
        int t = dlist[d];
        int hoff = h * 64;
        const float* xr = (t == i) ? (d_xrM + i * 128 + hoff) : (d_xr0 + t * 128 + hoff);
        auto rowfn = [&](int s) {
            return (s == i) ? (d_xlM + i * 128 + hoff) : (d_xl0 + s * 128 + hoff);
        };
        int b = d_rowptr[t], deg = d_rowptr[t + 1] - b;
        float2 o = gat_head(d_csrc, b, deg, rowfn, xr, att1 + hoff, lane);
        hA[d * 128 + hoff + c0] = o.x;
        hA[d * 128 + hoff + c0 + 1] = o.y;
    }
    __syncthreads();
    for (int idx = tid; idx < nd * 64; idx += 256) {
        int d = idx >> 6, c = idx & 63;
        float v = 0.5f * (hA[d * 128 + c] + hA[d * 128 + 64 + c]) + bias1[c];
        g1d[d * 64 + c] = v > 0.f ? v : expm1f(v);
    }
    __syncthreads();

    // Phase B: xl2 deltas + xr2 (warp tasks)
    int ntask = nd * 2 + 2;
    for (int task = wid; task < ntask; task += 8) {
        int isxr = (task >= nd * 2);
        int d = isxr ? 0 : (task >> 1);
        int hh = isxr ? (task - nd * 2) : (task & 1);
        int co = hh * 64 + c0;
        const float* W = isxr ? w2r : w2l;
        const float* bb = isxr ? b2r : b2l;
        float sxv = bb[co], syv = bb[co + 1];
        const float* g = g1d + d * 64;
        #pragma unroll 8
        for (int k = 0; k < 64; k++) {
            float gv = g[k];
            sxv += gv * W[k * 128 + co];
            syv += gv * W[k * 128 + co + 1];
        }
        if (isxr) { xr2s[co] = sxv; xr2s[co + 1] = syv; }
        else      { xl2d[d * 128 + co] = sxv; xl2d[d * 128 + co + 1] = syv; }
    }
    __syncthreads();

    // Phase C: layer-2 GAT at target i (warps 0,1 = heads)
    if (wid < 2) {
        int hoff = wid * 64;
        auto rowfn2 = [&](int s) -> const float* {
            int dd = didx[s];
            return (dd >= 0) ? (const float*)(xl2d + dd * 128 + hoff)
                             : (const float*)(d_xl20 + s * 128 + hoff);
        };
        float2 o = gat_head(d_csrc, b_i, deg_i, rowfn2,
                            (const float*)(xr2s + hoff), att2 + hoff, lane);
        hC[hoff + c0] = o.x;
        hC[hoff + c0 + 1] = o.y;
    }
    __syncthreads();
    if (tid < 64) {
        float v = 0.5f * (hC[tid] + hC[64 + tid]) + bias2[tid];
        g2[tid] = v > 0.f ? v : expm1f(v);
    }
    __syncthreads();

    // reconstruction row i
    if (tid < 64) {
        float a = recb[tid];
        #pragma unroll 8
        for (int c = 0; c < 64; c++) a += g2[c] * recw[c * 64 + tid];
        out[i * 64 + tid] = tanhf(a);
    }
}

// ---------------- launch ----------------
extern "C" void kernel_launch(void* const* d_in, const int* in_sizes, int n_in,
                              void* d_out, int out_size)
{
    const float* x          = (const float*)d_in[0];
    const float* E_emb      = (const float*)d_in[1];
    const int*   edge_index = (const int*)  d_in[2];
    const float* node_proj  = (const float*)d_in[3];
    const float* emb_proj   = (const float*)d_in[4];
    const float* conv_w0    = (const float*)d_in[5];
    const float* conv_w1    = (const float*)d_in[6];
    const float* conv_b     = (const float*)d_in[7];
    const float* lin2_w     = (const float*)d_in[8];
    const float* lin2_b     = (const float*)d_in[9];
    const float* masked_proj= (const float*)d_in[10];
    const float* normal_proj= (const float*)d_in[11];
    const float* g1_wl      = (const float*)d_in[12];
    const float* g1_bl      = (const float*)d_in[13];
    const float* g1_wr      = (const float*)d_in[14];
    const float* g1_br      = (const float*)d_in[15];
    const float* g1_att     = (const float*)d_in[16];
    const float* g1_bias    = (const float*)d_in[17];
    const float* g2_wl      = (const float*)d_in[18];
    const float* g2_bl      = (const float*)d_in[19];
    const float* g2_wr      = (const float*)d_in[20];
    const float* g2_br      = (const float*)d_in[21];
    const float* g2_att     = (const float*)d_in[22];
    const float* g2_bias    = (const float*)d_in[23];
    const float* rec_w      = (const float*)d_in[24];
    const float* rec_b      = (const float*)d_in[25];
    float* out = (float*)d_out;

    int E = in_sizes[2] / 2;

    cudaFuncSetAttribute(k1_precompute, cudaFuncAttributeMaxDynamicSharedMemorySize, 149504);

    k1_precompute<<<NN / 4, 256, 149504>>>(x, E_emb, node_proj, emb_proj,
                                           conv_w0, conv_w1, conv_b,
                                           lin2_w, lin2_b, masked_proj, normal_proj,
                                           g1_wl, g1_bl, g1_wr, g1_br);
    k2_csr<<<1, 1024>>>(edge_index, E);
    k3_baseline<<<NN / 4, 256>>>(g1_att, g1_bias, g2_wl, g2_bl);
    k4_main<<<NN, 256>>>(g1_att, g1_bias,
                         g2_wl, g2_bl, g2_wr, g2_br,
                         g2_att, g2_bias, rec_w, rec_b, out);
}